// round 1
// baseline (speedup 1.0000x reference)
#include <cuda_runtime.h>
#include <cuda_bf16.h>

// ChannelBlockImportanceGate: forward value == hard top-k block mask
// (straight-through soft term cancels to within 1 ulp).
//
// Shapes: features [8,256,132,132] f32, enabled int32 scalar.
// BLOCK=8 -> 17x17=289 blocks per channel (zero-padded edges), keep=72.

#define HH   132
#define WW   132
#define NBX  17
#define NBLK 289   // 17*17
#define KEEP 72    // round(289*0.25)
#define NPIX (HH*WW)
#define NTHREADS 256

__global__ __launch_bounds__(NTHREADS, 8)
void gate_kernel(const float* __restrict__ in,
                 const int*  __restrict__ enabled,
                 float* __restrict__ out)
{
    const int bc = blockIdx.x;                       // channel index in [0, B*C)
    const long long base = (long long)bc * NPIX;
    const int tid = threadIdx.x;

    if (*enabled == 0) {
        for (int p = tid; p < NPIX; p += NTHREADS)
            out[base + p] = 1.0f;
        return;
    }

    __shared__ float rbs[HH * NBX];    // per-row 8-wide block partial sums
    __shared__ float pooled[NBLK];     // block sums (scale-invariant: no /64 needed)
    __shared__ float hardm[NBLK];      // 0/1 mask per block

    const int warp = tid >> 5;
    const int lane = tid & 31;
    const float* src = in + base;

    // Phase A: each warp reduces rows (strided by 8) into 17 per-row block partials.
    // Coalesced loads; deterministic fixed-order shuffle reduction over 8-lane groups.
    for (int y = warp; y < HH; y += 8) {
        const float* row = src + y * WW;
        #pragma unroll
        for (int i = 0; i < 5; i++) {
            int x = i * 32 + lane;
            float v = (x < WW) ? fabsf(__ldg(row + x)) : 0.0f;
            v += __shfl_down_sync(0xffffffffu, v, 4);
            v += __shfl_down_sync(0xffffffffu, v, 2);
            v += __shfl_down_sync(0xffffffffu, v, 1);
            if ((lane & 7) == 0 && x < WW)
                rbs[y * NBX + (x >> 3)] = v;   // bx in [0,16], each written once
        }
    }
    __syncthreads();

    // Phase B: combine 8 row-partials into each block sum (rows >=132 are zero pad).
    for (int b = tid; b < NBLK; b += NTHREADS) {
        int by = b / NBX;
        int bx = b - by * NBX;
        int y0 = by * 8;
        float s = 0.0f;
        #pragma unroll
        for (int r = 0; r < 8; r++) {
            int y = y0 + r;
            if (y < HH) s += rbs[y * NBX + bx];
        }
        pooled[b] = s;
    }
    __syncthreads();

    // Phase C: stable rank (matches lax.top_k tie semantics: lower index wins).
    // rank_i = #{v_j > v_i} + #{j<i : v_j == v_i}; keep iff rank < KEEP.
    for (int b = tid; b < NBLK; b += NTHREADS) {
        float vi = pooled[b];
        int cnt = 0;
        #pragma unroll 4
        for (int j = 0; j < NBLK; j++) {
            float vj = pooled[j];               // broadcast smem read across threads
            cnt += (vj > vi) || (vj == vi && j < b);
        }
        hardm[b] = (cnt < KEEP) ? 1.0f : 0.0f;
    }
    __syncthreads();

    // Phase D: broadcast block mask to pixels, fully coalesced stores.
    for (int p = tid; p < NPIX; p += NTHREADS) {
        int y = p / WW;
        int x = p - y * WW;
        out[base + p] = hardm[(y >> 3) * NBX + (x >> 3)];
    }
}

extern "C" void kernel_launch(void* const* d_in, const int* in_sizes, int n_in,
                              void* d_out, int out_size)
{
    const float* features = (const float*)d_in[0];
    const int*   enabled  = (const int*)d_in[1];
    float* out = (float*)d_out;

    const int n_channels = out_size / NPIX;   // 8*256 = 2048
    gate_kernel<<<n_channels, NTHREADS>>>(features, enabled, out);
}

// round 2
// speedup vs baseline: 1.9306x; 1.9306x over previous
#include <cuda_runtime.h>
#include <cuda_bf16.h>

// ChannelBlockImportanceGate: forward value == hard top-k block mask
// (straight-through soft term cancels to within 1 ulp of the hard mask).
//
// features [8,256,132,132] f32, enabled int32. BLOCK=8 -> 17x17=289 blocks,
// keep = round(289*0.25) = 72. Ties: lower flat index wins (lax.top_k).
//
// R2: issue-bound fix. Vectorized loads/stores preserving the exact FP
// reduction tree of the R1-passing kernel; O(N^2) rank replaced by exact
// histogram-select (only boundary-bin items ranked pairwise).

#define HH   132
#define WW   132
#define NBX  17
#define NBLK 289
#define KEEP 72
#define NPIX (HH*WW)
#define NTHREADS 256

__global__ __launch_bounds__(NTHREADS, 8)
void gate_kernel(const float* __restrict__ in,
                 const int*  __restrict__ enabled,
                 float* __restrict__ out)
{
    const int bc = blockIdx.x;
    const long long base = (long long)bc * NPIX;
    const int tid  = threadIdx.x;
    const int warp = tid >> 5;
    const int lane = tid & 31;

    if (*enabled == 0) {
        float4 ones = make_float4(1.f, 1.f, 1.f, 1.f);
        float4* o4 = (float4*)(out + base);
        for (int p = tid; p < NPIX / 4; p += NTHREADS) o4[p] = ones;
        return;
    }

    __shared__ float rbs[HH * NBX];     // per-row 8-wide block partials
    __shared__ float pooled[NBLK];      // block sums
    __shared__ float hardm[NBLK];       // 0/1 mask
    __shared__ int   hist[32];
    __shared__ float wmin[8], wmax[8];
    __shared__ float s_minv, s_scale;
    __shared__ int   s_bb, s_chi, s_mcnt;
    __shared__ int   bblist[NBLK];

    if (tid < 32) hist[tid] = 0;
    if (tid == 0) s_mcnt = 0;

    const float* src = in + base;

    // ---- Phase A: row block-partials. Lane l (<17) owns block l of its row.
    // Sum tree identical to the R1 shuffle tree: ((v0+v4)+(v2+v6))+((v1+v5)+(v3+v7)).
    for (int y = warp; y < HH; y += 8) {
        if (lane < NBX) {
            const float* row = src + y * WW;
            float4 a = *(const float4*)(row + lane * 8);
            float4 b;
            if (lane < 16) b = *(const float4*)(row + lane * 8 + 4);
            else           b = make_float4(0.f, 0.f, 0.f, 0.f);
            float s = ((fabsf(a.x) + fabsf(b.x)) + (fabsf(a.z) + fabsf(b.z)))
                    + ((fabsf(a.y) + fabsf(b.y)) + (fabsf(a.w) + fabsf(b.w)));
            rbs[y * NBX + lane] = s;
        }
    }
    __syncthreads();

    // ---- Phase B: block sums (same linear order over 8 rows) + min/max.
    float lmin = 3.4e38f, lmax = -3.4e38f;
    for (int b = tid; b < NBLK; b += NTHREADS) {
        int by = b / NBX;
        int bx = b - by * NBX;
        int y0 = by * 8;
        float s = 0.0f;
        #pragma unroll
        for (int r = 0; r < 8; r++) {
            int y = y0 + r;
            if (y < HH) s += rbs[y * NBX + bx];
        }
        pooled[b] = s;
        lmin = fminf(lmin, s);
        lmax = fmaxf(lmax, s);
    }
    #pragma unroll
    for (int off = 16; off > 0; off >>= 1) {
        lmin = fminf(lmin, __shfl_down_sync(0xffffffffu, lmin, off));
        lmax = fmaxf(lmax, __shfl_down_sync(0xffffffffu, lmax, off));
    }
    if (lane == 0) { wmin[warp] = lmin; wmax[warp] = lmax; }
    __syncthreads();

    // ---- warp 0: global min/max -> bin scale
    if (warp == 0) {
        float mn = (lane < 8) ? wmin[lane] : 3.4e38f;
        float mx = (lane < 8) ? wmax[lane] : -3.4e38f;
        #pragma unroll
        for (int off = 4; off > 0; off >>= 1) {
            mn = fminf(mn, __shfl_down_sync(0xffffffffu, mn, off));
            mx = fmaxf(mx, __shfl_down_sync(0xffffffffu, mx, off));
        }
        if (lane == 0) {
            float r = mx - mn;
            s_minv  = mn;
            s_scale = (r > 0.0f) ? (32.0f / r) : 0.0f;
        }
    }
    __syncthreads();

    // ---- histogram of bins
    {
        float minv = s_minv, scale = s_scale;
        for (int b = tid; b < NBLK; b += NTHREADS) {
            int bin = (int)((pooled[b] - minv) * scale);
            bin = min(bin, 31);
            atomicAdd(&hist[bin], 1);
        }
    }
    __syncthreads();

    // ---- warp 0: suffix scan, find boundary bin bb containing the 72nd value
    if (warp == 0) {
        int cge = hist[lane];
        #pragma unroll
        for (int off = 1; off < 32; off <<= 1) {
            int t = __shfl_down_sync(0xffffffffu, cge, off);
            if (lane + off < 32) cge += t;
        }
        int cgt = __shfl_down_sync(0xffffffffu, cge, 1);
        if (lane == 31) cgt = 0;
        if (cgt < KEEP && cge >= KEEP) { s_bb = lane; s_chi = cgt; }
    }
    __syncthreads();

    // ---- classify: above bb -> 1, below -> 0, in bb -> exact rank needed
    {
        float minv = s_minv, scale = s_scale;
        int bb = s_bb;
        for (int b = tid; b < NBLK; b += NTHREADS) {
            int bin = (int)((pooled[b] - minv) * scale);
            bin = min(bin, 31);
            if (bin > bb)      hardm[b] = 1.0f;
            else if (bin < bb) hardm[b] = 0.0f;
            else               bblist[atomicAdd(&s_mcnt, 1)] = b;
        }
    }
    __syncthreads();

    // ---- exact rank among boundary-bin items (tie: lower index wins)
    {
        int m = s_mcnt;
        int budget = KEEP - s_chi;          // >= 1 by construction
        for (int it = tid; it < m; it += NTHREADS) {
            int i = bblist[it];
            float vi = pooled[i];
            int c = 0;
            for (int j = 0; j < m; j++) {
                int jj = bblist[j];
                float vj = pooled[jj];
                c += (vj > vi) || (vj == vi && jj < i);
            }
            hardm[i] = (c < budget) ? 1.0f : 0.0f;
        }
    }
    __syncthreads();

    // ---- Phase D: expand to pixels, float4 stores, no divisions
    for (int by = warp; by < NBX; by += 8) {
        float  mv  = hardm[by * NBX + (lane >> 1)];     // block for x = lane*4
        float  m16 = hardm[by * NBX + 16];              // tail block x=128..131
        float4 v4  = make_float4(mv, mv, mv, mv);
        float4 v16 = make_float4(m16, m16, m16, m16);
        int ylim = min(HH - by * 8, 8);
        float* obase = out + base + (by * 8) * WW;
        for (int r = 0; r < ylim; r++) {
            float* orow = obase + r * WW;
            *(float4*)(orow + lane * 4) = v4;
            if (lane == 0) *(float4*)(orow + 128) = v16;
        }
    }
}

extern "C" void kernel_launch(void* const* d_in, const int* in_sizes, int n_in,
                              void* d_out, int out_size)
{
    const float* features = (const float*)d_in[0];
    const int*   enabled  = (const int*)d_in[1];
    float* out = (float*)d_out;

    const int n_channels = out_size / NPIX;   // 2048
    gate_kernel<<<n_channels, NTHREADS>>>(features, enabled, out);
}